// round 1
// baseline (speedup 1.0000x reference)
#include <cuda_runtime.h>
#include <mma.h>
#include <cstdint>

using namespace nvcuda;

#define T_ 7
#define NTOK 36864            // B*H*W = 4*96*96
#define ROWS (T_ * NTOK)      // 258048
#define CDIM 256
#define NQKV 768

// Scratch (device globals — no allocation allowed in kernel_launch)
__device__ float g_qkv[(size_t)ROWS * NQKV];   // [t*NTOK+s][q(256)|k(256)|v(256)]
__device__ float g_ctx[(size_t)ROWS * CDIM];   // attention output
__device__ float g_wcat[CDIM * NQKV];          // [Wq | Wk | Wv], K-major
__device__ float g_bias[T_ * NQKV];            // per-t bias incl. t_emb@W terms

// ---------------------------------------------------------------------------
// Prep: pack weights and fold t_emb into per-t bias:
//   q = x@Wq + (t_emb[t]@Wq + bq),  k likewise,  v = x@Wv + bv
// ---------------------------------------------------------------------------
__global__ void prep_wcat_kernel(const float* __restrict__ Wq,
                                 const float* __restrict__ Wk,
                                 const float* __restrict__ Wv) {
    int i = blockIdx.x * blockDim.x + threadIdx.x;
    if (i >= CDIM * NQKV) return;
    int c = i / NQKV, n = i % NQKV;
    float v;
    if (n < 256)      v = Wq[c * 256 + n];
    else if (n < 512) v = Wk[c * 256 + (n - 256)];
    else              v = Wv[c * 256 + (n - 512)];
    g_wcat[i] = v;
}

__global__ void prep_bias_kernel(const float* __restrict__ te,
                                 const float* __restrict__ Wq,
                                 const float* __restrict__ bq,
                                 const float* __restrict__ Wk,
                                 const float* __restrict__ bk,
                                 const float* __restrict__ bv) {
    int i = blockIdx.x * blockDim.x + threadIdx.x;
    if (i >= T_ * NQKV) return;
    int t = i / NQKV, n = i % NQKV;
    float r;
    if (n < 512) {
        const float* W = (n < 256) ? Wq : Wk;
        int nn = n & 255;
        float acc = (n < 256) ? bq[nn] : bk[nn];
        for (int c = 0; c < CDIM; c++) acc += te[t * CDIM + c] * W[c * 256 + nn];
        r = acc;
    } else {
        r = bv[n - 512];
    }
    g_bias[i] = r;
}

// ---------------------------------------------------------------------------
// TF32 tiled GEMM: C[row][n] = A[row][k] * B[k][n] + bias
// A: [ROWS][256] row-major.  B: [256][NW] row-major.
// Block tile 128x128, K-chunk 32, 8 warps each computing 32x64 via wmma 16x16x8.
// grid = (NW/128, ROWS/128): x (N-blocks) fastest => A tile reuse hits L2.
// TSTRIDE!=0: bias indexed [t][n] with t = row_block/288 (36864/128 = 288 exact).
// ---------------------------------------------------------------------------
template<int NW, int TSTRIDE>
__global__ void gemm_tf32_kernel(const float* __restrict__ A,
                                 const float* __restrict__ B,
                                 const float* __restrict__ bias,
                                 float* __restrict__ Cout) {
    extern __shared__ float sm[];
    float* As = sm;              // [128][36]  (pad to 36)
    float* Bs = sm + 128 * 36;   // [32][132]  (pad to 132)
    float* Cs = sm;              // [128][132] (reused after k-loop)

    const int bn = blockIdx.x, bm = blockIdx.y;
    const int row0 = bm * 128, col0 = bn * 128;
    const int tid = threadIdx.x;
    const int wid = tid >> 5;
    const int wm = wid >> 1;     // 0..3 -> rows wm*32
    const int wn = wid & 1;      // 0..1 -> cols wn*64

    wmma::fragment<wmma::accumulator, 16, 16, 8, float> acc[2][4];
    #pragma unroll
    for (int i = 0; i < 2; i++)
        #pragma unroll
        for (int j = 0; j < 4; j++) wmma::fill_fragment(acc[i][j], 0.0f);

    for (int kc = 0; kc < CDIM / 32; kc++) {
        // Stage A chunk 128x32 (coalesced float4), convert to tf32
        #pragma unroll
        for (int i = 0; i < 4; i++) {
            int id = tid + i * 256;                 // 0..1023 float4 slots
            int r = id >> 3, c = (id & 7) * 4;
            const float4 v = *reinterpret_cast<const float4*>(
                A + (size_t)(row0 + r) * CDIM + kc * 32 + c);
            float* d = As + r * 36 + c;
            d[0] = wmma::__float_to_tf32(v.x);
            d[1] = wmma::__float_to_tf32(v.y);
            d[2] = wmma::__float_to_tf32(v.z);
            d[3] = wmma::__float_to_tf32(v.w);
        }
        // Stage B chunk 32x128
        #pragma unroll
        for (int i = 0; i < 4; i++) {
            int id = tid + i * 256;
            int r = id >> 5, c = (id & 31) * 4;
            const float4 v = *reinterpret_cast<const float4*>(
                B + (size_t)(kc * 32 + r) * NW + col0 + c);
            float* d = Bs + r * 132 + c;
            d[0] = wmma::__float_to_tf32(v.x);
            d[1] = wmma::__float_to_tf32(v.y);
            d[2] = wmma::__float_to_tf32(v.z);
            d[3] = wmma::__float_to_tf32(v.w);
        }
        __syncthreads();
        #pragma unroll
        for (int ks = 0; ks < 4; ks++) {
            const int k0 = ks * 8;
            wmma::fragment<wmma::matrix_a, 16, 16, 8, wmma::precision::tf32, wmma::row_major> a0, a1;
            wmma::load_matrix_sync(a0, As + (wm * 32) * 36 + k0, 36);
            wmma::load_matrix_sync(a1, As + (wm * 32 + 16) * 36 + k0, 36);
            #pragma unroll
            for (int j = 0; j < 4; j++) {
                wmma::fragment<wmma::matrix_b, 16, 16, 8, wmma::precision::tf32, wmma::row_major> b;
                wmma::load_matrix_sync(b, Bs + k0 * 132 + wn * 64 + j * 16, 132);
                wmma::mma_sync(acc[0][j], a0, b, acc[0][j]);
                wmma::mma_sync(acc[1][j], a1, b, acc[1][j]);
            }
        }
        __syncthreads();
    }

    // Epilogue: stage C in smem, add bias, write coalesced float4
    #pragma unroll
    for (int i = 0; i < 2; i++)
        #pragma unroll
        for (int j = 0; j < 4; j++)
            wmma::store_matrix_sync(Cs + (wm * 32 + i * 16) * 132 + wn * 64 + j * 16,
                                    acc[i][j], 132, wmma::mem_row_major);
    __syncthreads();

    const int t = TSTRIDE ? (bm / 288) : 0;
    #pragma unroll
    for (int i = 0; i < 16; i++) {
        int id = tid + i * 256;                     // 0..4095 float4 slots
        int r = id >> 5, c = (id & 31) * 4;
        float4 v = *reinterpret_cast<const float4*>(Cs + r * 132 + c);
        int n = col0 + c;
        const float4 bv4 = *reinterpret_cast<const float4*>(bias + t * TSTRIDE + n);
        v.x += bv4.x; v.y += bv4.y; v.z += bv4.z; v.w += bv4.w;
        *reinterpret_cast<float4*>(Cout + (size_t)(row0 + r) * NW + n) = v;
    }
}

// ---------------------------------------------------------------------------
// Attention over T=7 per (token, head). One warp handles one token and a
// group of 4 heads: lane = hg*8 + dg, each lane owns 4 dims (float4).
// Dots via 3-level shfl_xor within 8-lane groups; exp distributed across
// lanes (<=7 MUFU/lane); un-normalized accumulation + rcp at the end.
// Logits are small (inputs ~N(0,1)*0.02 weights) so no max-subtraction needed.
// ---------------------------------------------------------------------------
__global__ void attn_kernel() {
    const int gw = (blockIdx.x * blockDim.x + threadIdx.x) >> 5;
    const int lane = threadIdx.x & 31;
    const int s = gw >> 1;              // token
    const int half = gw & 1;            // head group of 4
    const int hg = lane >> 3, dg = lane & 7;
    const int col = (half * 4 + hg) * 32 + dg * 4;

    float4 q[7], k[7], v[7];
    #pragma unroll
    for (int t = 0; t < 7; t++) {
        const float* base = g_qkv + (size_t)(t * NTOK + s) * NQKV;
        q[t] = *reinterpret_cast<const float4*>(base + col);
        k[t] = *reinterpret_cast<const float4*>(base + 256 + col);
        v[t] = *reinterpret_cast<const float4*>(base + 512 + col);
    }

    const float scale = 0.17677669529663687f;  // 1/sqrt(32)
    float e[7] = {0.f, 0.f, 0.f, 0.f, 0.f, 0.f, 0.f};
    #pragma unroll
    for (int qt = 0; qt < 7; qt++) {
        #pragma unroll
        for (int t = 0; t < 7; t++) {
            float d = q[qt].x * k[t].x + q[qt].y * k[t].y
                    + q[qt].z * k[t].z + q[qt].w * k[t].w;
            d += __shfl_xor_sync(0xffffffffu, d, 1);
            d += __shfl_xor_sync(0xffffffffu, d, 2);
            d += __shfl_xor_sync(0xffffffffu, d, 4);
            const int p = qt * 7 + t;
            if ((p & 7) == dg) e[p >> 3] = __expf(d * scale);
        }
    }

    float4 ctx[7];
    float den[7];
    #pragma unroll
    for (int qt = 0; qt < 7; qt++) { ctx[qt] = make_float4(0, 0, 0, 0); den[qt] = 0.f; }
    #pragma unroll
    for (int qt = 0; qt < 7; qt++) {
        #pragma unroll
        for (int t = 0; t < 7; t++) {
            const int p = qt * 7 + t;
            float eb = __shfl_sync(0xffffffffu, e[p >> 3], p & 7, 8);  // within 8-lane group
            den[qt] += eb;
            ctx[qt].x += eb * v[t].x;
            ctx[qt].y += eb * v[t].y;
            ctx[qt].z += eb * v[t].z;
            ctx[qt].w += eb * v[t].w;
        }
    }
    #pragma unroll
    for (int qt = 0; qt < 7; qt++) {
        const float r = 1.0f / den[qt];
        float4 o = make_float4(ctx[qt].x * r, ctx[qt].y * r, ctx[qt].z * r, ctx[qt].w * r);
        *reinterpret_cast<float4*>(g_ctx + (size_t)(qt * NTOK + s) * CDIM + col) = o;
    }
}

// ---------------------------------------------------------------------------
extern "C" void kernel_launch(void* const* d_in, const int* /*in_sizes*/, int /*n_in*/,
                              void* d_out, int /*out_size*/) {
    const float* frames = (const float*)d_in[0];
    const float* temb   = (const float*)d_in[1];
    const float* Wq     = (const float*)d_in[2];
    const float* bq     = (const float*)d_in[3];
    const float* Wk     = (const float*)d_in[4];
    const float* bk     = (const float*)d_in[5];
    const float* Wv     = (const float*)d_in[6];
    const float* bv     = (const float*)d_in[7];
    const float* Wo     = (const float*)d_in[8];
    const float* bo     = (const float*)d_in[9];
    float* out = (float*)d_out;

    void *p_qkv, *p_ctx, *p_wcat, *p_bias;
    cudaGetSymbolAddress(&p_qkv,  g_qkv);
    cudaGetSymbolAddress(&p_ctx,  g_ctx);
    cudaGetSymbolAddress(&p_wcat, g_wcat);
    cudaGetSymbolAddress(&p_bias, g_bias);

    const int smem = 128 * 132 * 4;  // 67584 B
    cudaFuncSetAttribute(gemm_tf32_kernel<NQKV, NQKV>,
                         cudaFuncAttributeMaxDynamicSharedMemorySize, smem);
    cudaFuncSetAttribute(gemm_tf32_kernel<CDIM, 0>,
                         cudaFuncAttributeMaxDynamicSharedMemorySize, smem);

    prep_wcat_kernel<<<(CDIM * NQKV + 255) / 256, 256>>>(Wq, Wk, Wv);
    prep_bias_kernel<<<(T_ * NQKV + 255) / 256, 256>>>(temb, Wq, bq, Wk, bk, bv);

    // QKV projection: [258048 x 256] @ [256 x 768] + bias[t]
    gemm_tf32_kernel<NQKV, NQKV><<<dim3(NQKV / 128, ROWS / 128), 256, smem>>>(
        frames, (const float*)p_wcat, (const float*)p_bias, (float*)p_qkv);

    // Attention: 2 warps per token (4 heads each)
    attn_kernel<<<(NTOK * 2 * 32) / 256, 256>>>();

    // Output projection: ctx [258048 x 256] @ Wo [256 x 256] + bo
    gemm_tf32_kernel<CDIM, 0><<<dim3(CDIM / 128, ROWS / 128), 256, smem>>>(
        (const float*)p_ctx, Wo, bo, out);
}

// round 3
// speedup vs baseline: 2.4546x; 2.4546x over previous
#include <cuda_runtime.h>
#include <cstdint>

#define T_ 7
#define NTOK 36864            // B*H*W
#define ROWS (T_ * NTOK)      // 258048
#define CDIM 256
#define NQKV 768

// Scratch (device globals — no allocation allowed)
__device__ float g_qkv[(size_t)ROWS * NQKV];   // [t*NTOK+s][q|k|v]
__device__ float g_ctx[(size_t)ROWS * CDIM];   // attn out, pre-rounded to tf32
__device__ float g_wbt[NQKV * CDIM];           // [n][k], tf32-rounded
__device__ float g_wot[CDIM * CDIM];           // [c][nd], tf32-rounded
__device__ float g_bias[T_ * NQKV];

// ---------------------------------------------------------------------------
// Portable PTX helpers (NO sm_103a-only instructions: harness compiles via
// compute_103 virtual arch, so tcgen05/TMA-tensor are unavailable.)
// ---------------------------------------------------------------------------
__device__ __forceinline__ uint32_t smem_u32(const void* p) {
    uint32_t a;
    asm("{ .reg .u64 t; cvta.to.shared.u64 t, %1; cvt.u32.u64 %0, t; }" : "=r"(a) : "l"(p));
    return a;
}
__device__ __forceinline__ float ftf32(float x) {
    uint32_t r;
    asm("cvt.rn.tf32.f32 %0, %1;" : "=r"(r) : "f"(x));
    return __uint_as_float(r);
}
__device__ __forceinline__ void ldsm4(uint32_t* r, uint32_t addr) {
    asm volatile("ldmatrix.sync.aligned.m8n8.x4.shared.b16 {%0,%1,%2,%3}, [%4];"
        : "=r"(r[0]), "=r"(r[1]), "=r"(r[2]), "=r"(r[3]) : "r"(addr));
}
__device__ __forceinline__ void mma_tf32(float* d, const uint32_t* a, const uint32_t* b) {
    asm volatile("mma.sync.aligned.m16n8k8.row.col.f32.tf32.tf32.f32 "
        "{%0,%1,%2,%3}, {%4,%5,%6,%7}, {%8,%9}, {%0,%1,%2,%3};"
        : "+f"(d[0]), "+f"(d[1]), "+f"(d[2]), "+f"(d[3])
        : "r"(a[0]), "r"(a[1]), "r"(a[2]), "r"(a[3]), "r"(b[0]), "r"(b[1]));
}
#define CP_ASYNC16(dst, src) asm volatile("cp.async.cg.shared.global [%0], [%1], 16;" :: "r"(dst), "l"(src))
#define CP_COMMIT()          asm volatile("cp.async.commit_group;" ::: "memory")
#define CP_WAIT1()           asm volatile("cp.async.wait_group 1;" ::: "memory")
#define CP_WAIT0()           asm volatile("cp.async.wait_group 0;" ::: "memory")

#define STAGE_BYTES 49152u   // A 16KB + B 32KB per stage
#define SM_TOTAL (3 * STAGE_BYTES)   // 147456; epilogue 128x260 floats (133120) reuses it

// ---------------------------------------------------------------------------
// Prep kernels
// ---------------------------------------------------------------------------
__global__ void prep_wt_kernel(const float* __restrict__ Wq,
                               const float* __restrict__ Wk,
                               const float* __restrict__ Wv,
                               const float* __restrict__ Wo) {
    int i = blockIdx.x * blockDim.x + threadIdx.x;
    if (i < NQKV * CDIM) {
        int n = i / CDIM, c = i % CDIM;
        float v;
        if (n < 256)      v = Wq[c * 256 + n];
        else if (n < 512) v = Wk[c * 256 + (n - 256)];
        else              v = Wv[c * 256 + (n - 512)];
        g_wbt[i] = ftf32(v);
    } else if (i < NQKV * CDIM + CDIM * CDIM) {
        int j = i - NQKV * CDIM;
        int co = j / CDIM, nd = j % CDIM;
        g_wot[j] = ftf32(Wo[nd * 256 + co]);
    }
}

__global__ void prep_bias_kernel(const float* __restrict__ te,
                                 const float* __restrict__ Wq,
                                 const float* __restrict__ bq,
                                 const float* __restrict__ Wk,
                                 const float* __restrict__ bk,
                                 const float* __restrict__ bv) {
    int i = blockIdx.x * blockDim.x + threadIdx.x;
    if (i >= T_ * NQKV) return;
    int t = i / NQKV, n = i % NQKV;
    float r;
    if (n < 512) {
        const float* W = (n < 256) ? Wq : Wk;
        int nn = n & 255;
        float acc = (n < 256) ? bq[nn] : bk[nn];
        for (int c = 0; c < CDIM; c++) acc += te[t * CDIM + c] * W[c * 256 + nn];
        r = acc;
    } else {
        r = bv[n - 512];
    }
    g_bias[i] = r;
}

// ---------------------------------------------------------------------------
// mma.sync tf32 GEMM: C[row][n] = A[row][k] * Bt[n][k] + bias
// CTA tile 128(M) x 256(N), K=256 in 8 chunks of 32, 3-stage cp.async pipeline.
// 8 warps, warp tile 64x64 (4 m-tiles x 8 n-tiles of m16n8k8).
// Smem k-major SW128-swizzled; fragments via ldmatrix.x4 (tf32-as-b16 trick).
// A_CVT: A staged via LDG + cvt.rn.tf32 + STS (prefetched 2 chunks ahead);
// otherwise A comes pre-rounded and uses cp.async like B.
// ---------------------------------------------------------------------------
template<int NW, int TSTRIDE, bool A_CVT>
__global__ __launch_bounds__(256, 1)
void gemm_mma_kernel(const float* __restrict__ A,
                     const float* __restrict__ Bt,
                     const float* __restrict__ bias,
                     float* __restrict__ Cout) {
    extern __shared__ __align__(128) char smem[];
    const uint32_t sb = smem_u32(smem);

    const int tid  = threadIdx.x;
    const int lane = tid & 31, wid = tid >> 5;
    const int wm = wid >> 2;          // 0..1 : rows wm*64
    const int wn = wid & 3;           // 0..3 : cols wn*64
    const int row0 = blockIdx.y * 128;
    const int col0 = blockIdx.x * 256;

    // Fragment address components (SW128 swizzle xor uses row&7 = lane&7)
    const uint32_t fxor  = (uint32_t)(lane & 7) << 4;
    const uint32_t a_row = (uint32_t)(wm * 64 + (lane & 15)) * 128;
    const uint32_t ahalf = (uint32_t)(lane >> 4) * 16;
    const uint32_t b_row = (uint32_t)(wn * 64 + (lane & 7) + ((lane >> 4) << 3)) * 128;
    const uint32_t bhalf = (uint32_t)((lane >> 3) & 1) * 16;

    // Staging coordinates
    const int gA = tid;                       // A: 1024 granules, 4 per thread
    const int gB = tid;                       // B: 2048 granules, 8 per thread

    // ---- staging helpers ----
    auto stageB = [&](int kc, uint32_t nb) {
        #pragma unroll
        for (int i = 0; i < 8; i++) {
            int g = gB + i * 256;
            int r = g >> 3, c16 = g & 7;
            uint32_t dst = nb + 16384u + (uint32_t)r * 128 + (((uint32_t)c16 * 16) ^ (((uint32_t)(r & 7)) << 4));
            const float* src = Bt + (size_t)(col0 + r) * CDIM + kc * 32 + c16 * 4;
            CP_ASYNC16(dst, src);
        }
    };
    auto stageA_cp = [&](int kc, uint32_t nb) {
        #pragma unroll
        for (int i = 0; i < 4; i++) {
            int g = gA + i * 256;
            int r = g >> 3, c16 = g & 7;
            uint32_t dst = nb + (uint32_t)r * 128 + (((uint32_t)c16 * 16) ^ (((uint32_t)(r & 7)) << 4));
            const float* src = A + (size_t)(row0 + r) * CDIM + kc * 32 + c16 * 4;
            CP_ASYNC16(dst, src);
        }
    };
    auto ldgA = [&](int kc, float4* v) {
        #pragma unroll
        for (int i = 0; i < 4; i++) {
            int g = gA + i * 256;
            int r = g >> 3, c16 = g & 7;
            v[i] = *reinterpret_cast<const float4*>(A + (size_t)(row0 + r) * CDIM + kc * 32 + c16 * 4);
        }
    };
    auto stsA = [&](uint32_t nb, const float4* v) {
        #pragma unroll
        for (int i = 0; i < 4; i++) {
            int g = gA + i * 256;
            int r = g >> 3, c16 = g & 7;
            float4 t = v[i];
            t.x = ftf32(t.x); t.y = ftf32(t.y); t.z = ftf32(t.z); t.w = ftf32(t.w);
            uint32_t off = (nb - sb) + (uint32_t)r * 128 + (((uint32_t)c16 * 16) ^ (((uint32_t)(r & 7)) << 4));
            *reinterpret_cast<float4*>(smem + off) = t;
        }
    };

    // ---- prologue: stage chunks 0 and 1 ----
    if (A_CVT) {
        float4 p0[4], p1[4];
        ldgA(0, p0); ldgA(1, p1);
        stsA(sb + 0 * STAGE_BYTES, p0);
        stageB(0, sb + 0 * STAGE_BYTES); CP_COMMIT();
        stsA(sb + 1 * STAGE_BYTES, p1);
        stageB(1, sb + 1 * STAGE_BYTES); CP_COMMIT();
    } else {
        stageA_cp(0, sb); stageB(0, sb); CP_COMMIT();
        stageA_cp(1, sb + STAGE_BYTES); stageB(1, sb + STAGE_BYTES); CP_COMMIT();
    }

    float acc[4][8][4];
    #pragma unroll
    for (int mt = 0; mt < 4; mt++)
        #pragma unroll
        for (int nt = 0; nt < 8; nt++)
            #pragma unroll
            for (int e = 0; e < 4; e++) acc[mt][nt][e] = 0.0f;

    // ---- main loop ----
    #pragma unroll 1
    for (int kc = 0; kc < 8; kc++) {
        const uint32_t sbase = sb + (uint32_t)(kc % 3) * STAGE_BYTES;
        float4 apre[4];
        const bool pf = (kc < 6);
        if (A_CVT && pf) ldgA(kc + 2, apre);

        if (kc == 7) { CP_WAIT0(); } else { CP_WAIT1(); }
        __syncthreads();

        // compute chunk kc
        #pragma unroll
        for (int ks = 0; ks < 4; ks++) {
            uint32_t af[4][4];
            #pragma unroll
            for (int mt = 0; mt < 4; mt++)
                ldsm4(af[mt], sbase + a_row + (uint32_t)mt * 2048 + ((ahalf + ks * 32) ^ fxor));
            uint32_t bf[4][4];
            #pragma unroll
            for (int np = 0; np < 4; np++)
                ldsm4(bf[np], sbase + 16384u + b_row + (uint32_t)np * 2048 + ((bhalf + ks * 32) ^ fxor));
            #pragma unroll
            for (int mt = 0; mt < 4; mt++)
                #pragma unroll
                for (int nt = 0; nt < 8; nt++)
                    mma_tf32(acc[mt][nt], af[mt], &bf[nt >> 1][(nt & 1) * 2]);
        }

        if (pf) {
            const uint32_t nb = sb + (uint32_t)((kc + 2) % 3) * STAGE_BYTES;
            if (A_CVT) stsA(nb, apre); else stageA_cp(kc + 2, nb);
            stageB(kc + 2, nb);
            CP_COMMIT();
        }
    }
    __syncthreads();   // all warps done reading stage smem before epilogue reuse

    // ---- epilogue: acc -> smem -> coalesced global (+bias) ----
    float* Cs = reinterpret_cast<float*>(smem);   // [128][260]
    #pragma unroll
    for (int mt = 0; mt < 4; mt++) {
        const int r0 = wm * 64 + mt * 16 + (lane >> 2);
        #pragma unroll
        for (int nt = 0; nt < 8; nt++) {
            const int c0 = wn * 64 + nt * 8 + (lane & 3) * 2;
            *reinterpret_cast<float2*>(Cs + r0 * 260 + c0)       = make_float2(acc[mt][nt][0], acc[mt][nt][1]);
            *reinterpret_cast<float2*>(Cs + (r0 + 8) * 260 + c0) = make_float2(acc[mt][nt][2], acc[mt][nt][3]);
        }
    }
    __syncthreads();

    const int t = TSTRIDE ? (blockIdx.y / 288) : 0;
    #pragma unroll
    for (int i = 0; i < 32; i++) {
        int id = tid + i * 256;          // 8192 float4 slots
        int r = id >> 6, c = (id & 63) * 4;
        float4 v = *reinterpret_cast<const float4*>(Cs + r * 260 + c);
        int n = col0 + c;
        const float4 b4 = *reinterpret_cast<const float4*>(bias + t * TSTRIDE + n);
        v.x += b4.x; v.y += b4.y; v.z += b4.z; v.w += b4.w;
        *reinterpret_cast<float4*>(Cout + (size_t)(row0 + r) * NW + n) = v;
    }
}

// ---------------------------------------------------------------------------
// Attention over T=7 per (token, 4-head group). Output pre-rounded to tf32
// so GEMM2 can stage A via cp.async without conversion.
// ---------------------------------------------------------------------------
__global__ void attn_kernel() {
    const int gw = (blockIdx.x * blockDim.x + threadIdx.x) >> 5;
    const int lane = threadIdx.x & 31;
    const int s = gw >> 1;
    const int half = gw & 1;
    const int hg = lane >> 3, dg = lane & 7;
    const int col = (half * 4 + hg) * 32 + dg * 4;

    float4 q[7], k[7], v[7];
    #pragma unroll
    for (int t = 0; t < 7; t++) {
        const float* base = g_qkv + (size_t)(t * NTOK + s) * NQKV;
        q[t] = *reinterpret_cast<const float4*>(base + col);
        k[t] = *reinterpret_cast<const float4*>(base + 256 + col);
        v[t] = *reinterpret_cast<const float4*>(base + 512 + col);
    }

    const float scale = 0.17677669529663687f;
    float e[7] = {0.f, 0.f, 0.f, 0.f, 0.f, 0.f, 0.f};
    #pragma unroll
    for (int qt = 0; qt < 7; qt++) {
        #pragma unroll
        for (int t = 0; t < 7; t++) {
            float d = q[qt].x * k[t].x + q[qt].y * k[t].y
                    + q[qt].z * k[t].z + q[qt].w * k[t].w;
            d += __shfl_xor_sync(0xffffffffu, d, 1);
            d += __shfl_xor_sync(0xffffffffu, d, 2);
            d += __shfl_xor_sync(0xffffffffu, d, 4);
            const int p = qt * 7 + t;
            if ((p & 7) == dg) e[p >> 3] = __expf(d * scale);
        }
    }

    float4 ctx[7];
    float den[7];
    #pragma unroll
    for (int qt = 0; qt < 7; qt++) { ctx[qt] = make_float4(0, 0, 0, 0); den[qt] = 0.f; }
    #pragma unroll
    for (int qt = 0; qt < 7; qt++) {
        #pragma unroll
        for (int t = 0; t < 7; t++) {
            const int p = qt * 7 + t;
            float eb = __shfl_sync(0xffffffffu, e[p >> 3], p & 7, 8);
            den[qt] += eb;
            ctx[qt].x += eb * v[t].x;
            ctx[qt].y += eb * v[t].y;
            ctx[qt].z += eb * v[t].z;
            ctx[qt].w += eb * v[t].w;
        }
    }
    #pragma unroll
    for (int qt = 0; qt < 7; qt++) {
        const float r = 1.0f / den[qt];
        float4 o = make_float4(ftf32(ctx[qt].x * r), ftf32(ctx[qt].y * r),
                               ftf32(ctx[qt].z * r), ftf32(ctx[qt].w * r));
        *reinterpret_cast<float4*>(g_ctx + (size_t)(qt * NTOK + s) * CDIM + col) = o;
    }
}

// ---------------------------------------------------------------------------
extern "C" void kernel_launch(void* const* d_in, const int* /*in_sizes*/, int /*n_in*/,
                              void* d_out, int /*out_size*/) {
    const float* frames = (const float*)d_in[0];
    const float* temb   = (const float*)d_in[1];
    const float* Wq     = (const float*)d_in[2];
    const float* bq     = (const float*)d_in[3];
    const float* Wk     = (const float*)d_in[4];
    const float* bk     = (const float*)d_in[5];
    const float* Wv     = (const float*)d_in[6];
    const float* bv     = (const float*)d_in[7];
    const float* Wo     = (const float*)d_in[8];
    const float* bo     = (const float*)d_in[9];
    float* out = (float*)d_out;

    void *p_qkv, *p_ctx, *p_wbt, *p_wot, *p_bias;
    cudaGetSymbolAddress(&p_qkv,  g_qkv);
    cudaGetSymbolAddress(&p_ctx,  g_ctx);
    cudaGetSymbolAddress(&p_wbt,  g_wbt);
    cudaGetSymbolAddress(&p_wot,  g_wot);
    cudaGetSymbolAddress(&p_bias, g_bias);

    cudaFuncSetAttribute(gemm_mma_kernel<NQKV, NQKV, true>,
                         cudaFuncAttributeMaxDynamicSharedMemorySize, SM_TOTAL);
    cudaFuncSetAttribute(gemm_mma_kernel<CDIM, 0, false>,
                         cudaFuncAttributeMaxDynamicSharedMemorySize, SM_TOTAL);

    prep_wt_kernel<<<(NQKV * CDIM + CDIM * CDIM + 255) / 256, 256>>>(Wq, Wk, Wv, Wo);
    prep_bias_kernel<<<(T_ * NQKV + 255) / 256, 256>>>(temb, Wq, bq, Wk, bk, bv);

    // QKV projection: [258048 x 256] @ [256 x 768] + bias[t]
    gemm_mma_kernel<NQKV, NQKV, true><<<dim3(3, ROWS / 128), 256, SM_TOTAL>>>(
        frames, (const float*)p_wbt, (const float*)p_bias, (float*)p_qkv);

    // Attention
    attn_kernel<<<(NTOK * 2 * 32) / 256, 256>>>();

    // Output projection: [258048 x 256] @ [256 x 256] + bo
    gemm_mma_kernel<CDIM, 0, false><<<dim3(1, ROWS / 128), 256, SM_TOTAL>>>(
        (const float*)p_ctx, (const float*)p_wot, bo, out);
}

// round 4
// speedup vs baseline: 3.1844x; 1.2973x over previous
#include <cuda_runtime.h>
#include <cuda_fp16.h>
#include <cstdint>

#define T_ 7
#define NTOK 36864            // B*H*W
#define ROWS (T_ * NTOK)      // 258048
#define CDIM 256
#define NQKV 768

// Scratch (device globals — no allocation allowed)
__device__ __half g_a_h[(size_t)ROWS * CDIM];    // frames, fp16
__device__ __half g_qkv_h[(size_t)ROWS * NQKV];  // [t*NTOK+s][q|k|v], fp16
__device__ __half g_ctx_h[(size_t)ROWS * CDIM];  // attn out, fp16
__device__ __half g_wbt_h[NQKV * CDIM];          // [n][k], fp16
__device__ __half g_wot_h[CDIM * CDIM];          // [c][nd], fp16
__device__ float  g_bias[T_ * NQKV];

// ---------------------------------------------------------------------------
// Portable PTX helpers (compute_103 virtual arch — no tcgen05/TMA-tensor)
// ---------------------------------------------------------------------------
__device__ __forceinline__ uint32_t smem_u32(const void* p) {
    uint32_t a;
    asm("{ .reg .u64 t; cvta.to.shared.u64 t, %1; cvt.u32.u64 %0, t; }" : "=r"(a) : "l"(p));
    return a;
}
__device__ __forceinline__ void ldsm4(uint32_t* r, uint32_t addr) {
    asm volatile("ldmatrix.sync.aligned.m8n8.x4.shared.b16 {%0,%1,%2,%3}, [%4];"
        : "=r"(r[0]), "=r"(r[1]), "=r"(r[2]), "=r"(r[3]) : "r"(addr));
}
__device__ __forceinline__ void mma_f16(float* d, const uint32_t* a, const uint32_t* b) {
    asm volatile("mma.sync.aligned.m16n8k16.row.col.f32.f16.f16.f32 "
        "{%0,%1,%2,%3}, {%4,%5,%6,%7}, {%8,%9}, {%0,%1,%2,%3};"
        : "+f"(d[0]), "+f"(d[1]), "+f"(d[2]), "+f"(d[3])
        : "r"(a[0]), "r"(a[1]), "r"(a[2]), "r"(a[3]), "r"(b[0]), "r"(b[1]));
}
#define CP_ASYNC16(dst, src) asm volatile("cp.async.cg.shared.global [%0], [%1], 16;" :: "r"(dst), "l"(src))
#define CP_COMMIT()          asm volatile("cp.async.commit_group;" ::: "memory")
#define CP_WAIT1()           asm volatile("cp.async.wait_group 1;" ::: "memory")
#define CP_WAIT0()           asm volatile("cp.async.wait_group 0;" ::: "memory")

__device__ __forceinline__ uint2 f4_to_h4(float4 v) {
    __half2 h0 = __float22half2_rn(make_float2(v.x, v.y));
    __half2 h1 = __float22half2_rn(make_float2(v.z, v.w));
    uint2 r;
    r.x = *reinterpret_cast<uint32_t*>(&h0);
    r.y = *reinterpret_cast<uint32_t*>(&h1);
    return r;
}
__device__ __forceinline__ float4 h4_to_f4(uint2 u) {
    __half2 h0 = *reinterpret_cast<__half2*>(&u.x);
    __half2 h1 = *reinterpret_cast<__half2*>(&u.y);
    float2 a = __half22float2(h0), b = __half22float2(h1);
    return make_float4(a.x, a.y, b.x, b.y);
}

#define STAGE_BYTES 49152u    // A 16KB(fp16 128x64) + B 32KB(fp16 256x64) per stage
#define SM_TOTAL (3 * STAGE_BYTES)   // 147456; epilogue reuses as f32[128][260]

// ---------------------------------------------------------------------------
// Prep kernels
// ---------------------------------------------------------------------------
__global__ void prep_frames_kernel(const float* __restrict__ frames) {
    size_t i = (size_t)blockIdx.x * blockDim.x + threadIdx.x;   // float4 slot
    const float4 v = reinterpret_cast<const float4*>(frames)[i];
    reinterpret_cast<uint2*>(g_a_h)[i] = f4_to_h4(v);
}

__global__ void prep_wt_kernel(const float* __restrict__ Wq,
                               const float* __restrict__ Wk,
                               const float* __restrict__ Wv,
                               const float* __restrict__ Wo) {
    int i = blockIdx.x * blockDim.x + threadIdx.x;
    if (i < NQKV * CDIM) {
        int n = i / CDIM, c = i % CDIM;
        float v;
        if (n < 256)      v = Wq[c * 256 + n];
        else if (n < 512) v = Wk[c * 256 + (n - 256)];
        else              v = Wv[c * 256 + (n - 512)];
        g_wbt_h[i] = __float2half_rn(v);
    } else if (i < NQKV * CDIM + CDIM * CDIM) {
        int j = i - NQKV * CDIM;
        int co = j / CDIM, nd = j % CDIM;
        g_wot_h[j] = __float2half_rn(Wo[nd * 256 + co]);
    }
}

__global__ void prep_bias_kernel(const float* __restrict__ te,
                                 const float* __restrict__ Wq,
                                 const float* __restrict__ bq,
                                 const float* __restrict__ Wk,
                                 const float* __restrict__ bk,
                                 const float* __restrict__ bv) {
    int i = blockIdx.x * blockDim.x + threadIdx.x;
    if (i >= T_ * NQKV) return;
    int t = i / NQKV, n = i % NQKV;
    float r;
    if (n < 512) {
        const float* W = (n < 256) ? Wq : Wk;
        int nn = n & 255;
        float acc = (n < 256) ? bq[nn] : bk[nn];
        for (int c = 0; c < CDIM; c++) acc += te[t * CDIM + c] * W[c * 256 + nn];
        r = acc;
    } else {
        r = bv[n - 512];
    }
    g_bias[i] = r;
}

// ---------------------------------------------------------------------------
// fp16 mma.sync GEMM: C[row][n] = A[row][k] * Bt[n][k] + bias
// CTA 128(M) x 256(N), K=256 in 4 chunks of 64, 3-stage cp.async pipeline.
// 8 warps, warp tile 64x64 (4 m x 8 n of m16n8k16).
// Smem k-major, 128B rows, SW128 swizzle; fragments via ldmatrix.x4.
// ---------------------------------------------------------------------------
template<int NW, int TSTRIDE, bool OUT_HALF>
__global__ __launch_bounds__(256, 1)
void gemm_h_kernel(const __half* __restrict__ A,
                   const __half* __restrict__ Bt,
                   const float* __restrict__ bias,
                   void* __restrict__ Cout) {
    extern __shared__ __align__(128) char smem[];
    const uint32_t sb = smem_u32(smem);

    const int tid  = threadIdx.x;
    const int lane = tid & 31, wid = tid >> 5;
    const int wm = wid >> 2;          // 0..1 : rows wm*64
    const int wn = wid & 3;           // 0..3 : cols wn*64
    const int row0 = blockIdx.y * 128;
    const int col0 = blockIdx.x * 256;

    // Fragment addressing (SW128 xor pattern; addressed row &7 == lane&7)
    const uint32_t fxor  = (uint32_t)(lane & 7) << 4;
    const uint32_t a_row = (uint32_t)(wm * 64 + (lane & 15)) * 128;
    const uint32_t ahalf = (uint32_t)(lane >> 4) * 16;
    const uint32_t b_row = (uint32_t)(wn * 64 + (lane & 7) + ((lane >> 4) << 3)) * 128;
    const uint32_t bhalf = (uint32_t)((lane >> 3) & 1) * 16;

    auto stageA = [&](int kc, uint32_t nb) {
        #pragma unroll
        for (int i = 0; i < 4; i++) {
            int g = tid + i * 256;                 // 1024 granules (128 rows x 8)
            int r = g >> 3, c16 = g & 7;
            uint32_t dst = nb + (uint32_t)r * 128 + (((uint32_t)c16 * 16) ^ (((uint32_t)(r & 7)) << 4));
            const __half* src = A + (size_t)(row0 + r) * CDIM + kc * 64 + c16 * 8;
            CP_ASYNC16(dst, src);
        }
    };
    auto stageB = [&](int kc, uint32_t nb) {
        #pragma unroll
        for (int i = 0; i < 8; i++) {
            int g = tid + i * 256;                 // 2048 granules (256 rows x 8)
            int r = g >> 3, c16 = g & 7;
            uint32_t dst = nb + 16384u + (uint32_t)r * 128 + (((uint32_t)c16 * 16) ^ (((uint32_t)(r & 7)) << 4));
            const __half* src = Bt + (size_t)(col0 + r) * CDIM + kc * 64 + c16 * 8;
            CP_ASYNC16(dst, src);
        }
    };

    // prologue: stage chunks 0, 1
    stageA(0, sb);               stageB(0, sb);               CP_COMMIT();
    stageA(1, sb + STAGE_BYTES); stageB(1, sb + STAGE_BYTES); CP_COMMIT();

    float acc[4][8][4];
    #pragma unroll
    for (int mt = 0; mt < 4; mt++)
        #pragma unroll
        for (int nt = 0; nt < 8; nt++)
            #pragma unroll
            for (int e = 0; e < 4; e++) acc[mt][nt][e] = 0.0f;

    #pragma unroll 1
    for (int kc = 0; kc < 4; kc++) {
        const uint32_t sbase = sb + (uint32_t)(kc % 3) * STAGE_BYTES;
        if (kc == 3) { CP_WAIT0(); } else { CP_WAIT1(); }
        __syncthreads();

        #pragma unroll
        for (int ks = 0; ks < 4; ks++) {
            uint32_t af[4][4];
            #pragma unroll
            for (int mt = 0; mt < 4; mt++)
                ldsm4(af[mt], sbase + a_row + (uint32_t)mt * 2048 + ((ahalf + ks * 32) ^ fxor));
            uint32_t bf[4][4];
            #pragma unroll
            for (int np = 0; np < 4; np++)
                ldsm4(bf[np], sbase + 16384u + b_row + (uint32_t)np * 2048 + ((bhalf + ks * 32) ^ fxor));
            #pragma unroll
            for (int mt = 0; mt < 4; mt++)
                #pragma unroll
                for (int nt = 0; nt < 8; nt++)
                    mma_f16(acc[mt][nt], af[mt], &bf[nt >> 1][(nt & 1) * 2]);
        }

        if (kc < 2) {
            const uint32_t nb = sb + (uint32_t)((kc + 2) % 3) * STAGE_BYTES;
            stageA(kc + 2, nb);
            stageB(kc + 2, nb);
            CP_COMMIT();
        }
    }
    __syncthreads();

    // epilogue: frags -> smem f32 -> coalesced global (+bias)
    float* Cs = reinterpret_cast<float*>(smem);    // [128][260]
    #pragma unroll
    for (int mt = 0; mt < 4; mt++) {
        const int r0 = wm * 64 + mt * 16 + (lane >> 2);
        #pragma unroll
        for (int nt = 0; nt < 8; nt++) {
            const int c0 = wn * 64 + nt * 8 + (lane & 3) * 2;
            *reinterpret_cast<float2*>(Cs + r0 * 260 + c0)       = make_float2(acc[mt][nt][0], acc[mt][nt][1]);
            *reinterpret_cast<float2*>(Cs + (r0 + 8) * 260 + c0) = make_float2(acc[mt][nt][2], acc[mt][nt][3]);
        }
    }
    __syncthreads();

    const int t = TSTRIDE ? (blockIdx.y / 288) : 0;
    #pragma unroll
    for (int i = 0; i < 32; i++) {
        int id = tid + i * 256;                    // 8192 float4 slots
        int r = id >> 6, c = (id & 63) * 4;
        float4 v = *reinterpret_cast<const float4*>(Cs + r * 260 + c);
        int n = col0 + c;
        const float4 b4 = *reinterpret_cast<const float4*>(bias + t * TSTRIDE + n);
        v.x += b4.x; v.y += b4.y; v.z += b4.z; v.w += b4.w;
        if (OUT_HALF) {
            *reinterpret_cast<uint2*>(reinterpret_cast<__half*>(Cout) + (size_t)(row0 + r) * NW + n) = f4_to_h4(v);
        } else {
            *reinterpret_cast<float4*>(reinterpret_cast<float*>(Cout) + (size_t)(row0 + r) * NW + n) = v;
        }
    }
}

// ---------------------------------------------------------------------------
// Attention over T=7 per (token, 4-head group), fp16 in / fp16 out.
// Lane = (head-of-4, 8 dim-groups of 4); dots via 3-level shfl within 8 lanes;
// exp distributed (<=7 MUFU/lane); un-normalized accumulate + 1 rcp per row.
// ---------------------------------------------------------------------------
__global__ void attn_kernel() {
    const int gw = (blockIdx.x * blockDim.x + threadIdx.x) >> 5;
    const int lane = threadIdx.x & 31;
    const int s = gw >> 1;
    const int half = gw & 1;
    const int hg = lane >> 3, dg = lane & 7;
    const int col = (half * 4 + hg) * 32 + dg * 4;

    float4 q[7], k[7], v[7];
    #pragma unroll
    for (int t = 0; t < 7; t++) {
        const __half* base = g_qkv_h + (size_t)(t * NTOK + s) * NQKV;
        q[t] = h4_to_f4(*reinterpret_cast<const uint2*>(base + col));
        k[t] = h4_to_f4(*reinterpret_cast<const uint2*>(base + 256 + col));
        v[t] = h4_to_f4(*reinterpret_cast<const uint2*>(base + 512 + col));
    }

    const float scale = 0.17677669529663687f;  // 1/sqrt(32)
    float e[7] = {0.f, 0.f, 0.f, 0.f, 0.f, 0.f, 0.f};
    #pragma unroll
    for (int qt = 0; qt < 7; qt++) {
        #pragma unroll
        for (int t = 0; t < 7; t++) {
            float d = q[qt].x * k[t].x + q[qt].y * k[t].y
                    + q[qt].z * k[t].z + q[qt].w * k[t].w;
            d += __shfl_xor_sync(0xffffffffu, d, 1);
            d += __shfl_xor_sync(0xffffffffu, d, 2);
            d += __shfl_xor_sync(0xffffffffu, d, 4);
            const int p = qt * 7 + t;
            if ((p & 7) == dg) e[p >> 3] = __expf(d * scale);
        }
    }

    float4 ctx[7];
    float den[7];
    #pragma unroll
    for (int qt = 0; qt < 7; qt++) { ctx[qt] = make_float4(0, 0, 0, 0); den[qt] = 0.f; }
    #pragma unroll
    for (int qt = 0; qt < 7; qt++) {
        #pragma unroll
        for (int t = 0; t < 7; t++) {
            const int p = qt * 7 + t;
            float eb = __shfl_sync(0xffffffffu, e[p >> 3], p & 7, 8);
            den[qt] += eb;
            ctx[qt].x += eb * v[t].x;
            ctx[qt].y += eb * v[t].y;
            ctx[qt].z += eb * v[t].z;
            ctx[qt].w += eb * v[t].w;
        }
    }
    #pragma unroll
    for (int qt = 0; qt < 7; qt++) {
        const float r = 1.0f / den[qt];
        float4 o = make_float4(ctx[qt].x * r, ctx[qt].y * r, ctx[qt].z * r, ctx[qt].w * r);
        *reinterpret_cast<uint2*>(g_ctx_h + (size_t)(qt * NTOK + s) * CDIM + col) = f4_to_h4(o);
    }
}

// ---------------------------------------------------------------------------
extern "C" void kernel_launch(void* const* d_in, const int* /*in_sizes*/, int /*n_in*/,
                              void* d_out, int /*out_size*/) {
    const float* frames = (const float*)d_in[0];
    const float* temb   = (const float*)d_in[1];
    const float* Wq     = (const float*)d_in[2];
    const float* bq     = (const float*)d_in[3];
    const float* Wk     = (const float*)d_in[4];
    const float* bk     = (const float*)d_in[5];
    const float* Wv     = (const float*)d_in[6];
    const float* bv     = (const float*)d_in[7];
    const float* Wo     = (const float*)d_in[8];
    const float* bo     = (const float*)d_in[9];
    float* out = (float*)d_out;

    void *p_ah, *p_qkv, *p_ctx, *p_wbt, *p_wot, *p_bias;
    cudaGetSymbolAddress(&p_ah,   g_a_h);
    cudaGetSymbolAddress(&p_qkv,  g_qkv_h);
    cudaGetSymbolAddress(&p_ctx,  g_ctx_h);
    cudaGetSymbolAddress(&p_wbt,  g_wbt_h);
    cudaGetSymbolAddress(&p_wot,  g_wot_h);
    cudaGetSymbolAddress(&p_bias, g_bias);

    cudaFuncSetAttribute(gemm_h_kernel<NQKV, NQKV, true>,
                         cudaFuncAttributeMaxDynamicSharedMemorySize, SM_TOTAL);
    cudaFuncSetAttribute(gemm_h_kernel<CDIM, 0, false>,
                         cudaFuncAttributeMaxDynamicSharedMemorySize, SM_TOTAL);

    prep_wt_kernel<<<(NQKV * CDIM + CDIM * CDIM + 255) / 256, 256>>>(Wq, Wk, Wv, Wo);
    prep_bias_kernel<<<(T_ * NQKV + 255) / 256, 256>>>(temb, Wq, bq, Wk, bk, bv);
    prep_frames_kernel<<<(ROWS * CDIM / 4) / 256, 256>>>(frames);

    // QKV projection: [258048 x 256] @ [256 x 768] + bias[t]  -> fp16 qkv
    gemm_h_kernel<NQKV, NQKV, true><<<dim3(3, ROWS / 128), 256, SM_TOTAL>>>(
        (const __half*)p_ah, (const __half*)p_wbt, (const float*)p_bias, p_qkv);

    // Attention (fp16 -> fp16)
    attn_kernel<<<(NTOK * 2 * 32) / 256, 256>>>();

    // Output projection: [258048 x 256] @ [256 x 256] + bo -> f32 out
    gemm_h_kernel<CDIM, 0, false><<<dim3(1, ROWS / 128), 256, SM_TOTAL>>>(
        (const __half*)p_ctx, (const __half*)p_wot, bo, out);
}

// round 5
// speedup vs baseline: 3.5139x; 1.1035x over previous
#include <cuda_runtime.h>
#include <cuda_fp16.h>
#include <cstdint>

#define T_ 7
#define NTOK 36864            // B*H*W
#define ROWS (T_ * NTOK)      // 258048
#define CDIM 256
#define NQKV 768

// Scratch (device globals — no allocation allowed)
__device__ __half g_a_h[(size_t)ROWS * CDIM];    // frames, fp16
__device__ __half g_qkv_h[(size_t)ROWS * NQKV];  // [t*NTOK+s][q|k|v], fp16
__device__ __half g_ctx_h[(size_t)ROWS * CDIM];  // attn out, fp16
__device__ __half g_wbt_h[NQKV * CDIM];          // [n][k], fp16
__device__ __half g_wot_h[CDIM * CDIM];          // [c][nd], fp16
__device__ float  g_bias[T_ * NQKV];

// ---------------------------------------------------------------------------
// Portable PTX helpers (compute_103 virtual arch — no tcgen05/TMA-tensor)
// ---------------------------------------------------------------------------
__device__ __forceinline__ uint32_t smem_u32(const void* p) {
    uint32_t a;
    asm("{ .reg .u64 t; cvta.to.shared.u64 t, %1; cvt.u32.u64 %0, t; }" : "=r"(a) : "l"(p));
    return a;
}
__device__ __forceinline__ void ldsm4(uint32_t* r, uint32_t addr) {
    asm volatile("ldmatrix.sync.aligned.m8n8.x4.shared.b16 {%0,%1,%2,%3}, [%4];"
        : "=r"(r[0]), "=r"(r[1]), "=r"(r[2]), "=r"(r[3]) : "r"(addr));
}
__device__ __forceinline__ void mma_f16(float* d, const uint32_t* a, const uint32_t* b) {
    asm volatile("mma.sync.aligned.m16n8k16.row.col.f32.f16.f16.f32 "
        "{%0,%1,%2,%3}, {%4,%5,%6,%7}, {%8,%9}, {%0,%1,%2,%3};"
        : "+f"(d[0]), "+f"(d[1]), "+f"(d[2]), "+f"(d[3])
        : "r"(a[0]), "r"(a[1]), "r"(a[2]), "r"(a[3]), "r"(b[0]), "r"(b[1]));
}
#define CP_ASYNC16(dst, src) asm volatile("cp.async.cg.shared.global [%0], [%1], 16;" :: "r"(dst), "l"(src))
#define CP_COMMIT()          asm volatile("cp.async.commit_group;" ::: "memory")
#define CP_WAIT1()           asm volatile("cp.async.wait_group 1;" ::: "memory")
#define CP_WAIT0()           asm volatile("cp.async.wait_group 0;" ::: "memory")

__device__ __forceinline__ uint2 f4_to_h4(float4 v) {
    __half2 h0 = __float22half2_rn(make_float2(v.x, v.y));
    __half2 h1 = __float22half2_rn(make_float2(v.z, v.w));
    uint2 r;
    r.x = *reinterpret_cast<uint32_t*>(&h0);
    r.y = *reinterpret_cast<uint32_t*>(&h1);
    return r;
}
__device__ __forceinline__ float4 h4_to_f4(uint2 u) {
    __half2 h0 = *reinterpret_cast<__half2*>(&u.x);
    __half2 h1 = *reinterpret_cast<__half2*>(&u.y);
    float2 a = __half22float2(h0), b = __half22float2(h1);
    return make_float4(a.x, a.y, b.x, b.y);
}

#define STAGE_BYTES 32768u    // A 16KB (128x64 fp16) + B 16KB (128x64 fp16)
#define SM_TOTAL (3 * STAGE_BYTES)   // 98304; epilogue reuses as f32[128][132]

// ---------------------------------------------------------------------------
// Prep kernels
// ---------------------------------------------------------------------------
__global__ void prep_frames_kernel(const float* __restrict__ frames) {
    size_t i = (size_t)blockIdx.x * blockDim.x + threadIdx.x;   // float4 slot
    const float4 v = reinterpret_cast<const float4*>(frames)[i];
    reinterpret_cast<uint2*>(g_a_h)[i] = f4_to_h4(v);
}

__global__ void prep_wt_kernel(const float* __restrict__ Wq,
                               const float* __restrict__ Wk,
                               const float* __restrict__ Wv,
                               const float* __restrict__ Wo) {
    int i = blockIdx.x * blockDim.x + threadIdx.x;
    if (i < NQKV * CDIM) {
        int n = i / CDIM, c = i % CDIM;
        float v;
        if (n < 256)      v = Wq[c * 256 + n];
        else if (n < 512) v = Wk[c * 256 + (n - 256)];
        else              v = Wv[c * 256 + (n - 512)];
        g_wbt_h[i] = __float2half_rn(v);
    } else if (i < NQKV * CDIM + CDIM * CDIM) {
        int j = i - NQKV * CDIM;
        int co = j / CDIM, nd = j % CDIM;
        g_wot_h[j] = __float2half_rn(Wo[nd * 256 + co]);
    }
}

__global__ void prep_bias_kernel(const float* __restrict__ te,
                                 const float* __restrict__ Wq,
                                 const float* __restrict__ bq,
                                 const float* __restrict__ Wk,
                                 const float* __restrict__ bk,
                                 const float* __restrict__ bv) {
    int i = blockIdx.x * blockDim.x + threadIdx.x;
    if (i >= T_ * NQKV) return;
    int t = i / NQKV, n = i % NQKV;
    float r;
    if (n < 512) {
        const float* W = (n < 256) ? Wq : Wk;
        int nn = n & 255;
        float acc = (n < 256) ? bq[nn] : bk[nn];
        for (int c = 0; c < CDIM; c++) acc += te[t * CDIM + c] * W[c * 256 + nn];
        r = acc;
    } else {
        r = bv[n - 512];
    }
    g_bias[i] = r;
}

// ---------------------------------------------------------------------------
// fp16 mma.sync GEMM: C[row][n] = A[row][k] * Bt[n][k] + bias
// CTA 128(M) x 128(N), K=256 in 4 chunks of 64, 3-stage cp.async pipeline.
// 8 warps, warp tile 32x64 (2 m x 8 n of m16n8k16) -> acc 64 regs/thread,
// __launch_bounds__(256,2) forces <=128 regs so 2 CTAs co-reside per SM
// (2 x 96KB smem = 192KB < 228KB). Concurrency covers sync/pipeline bubbles.
// ---------------------------------------------------------------------------
template<int NW, int TSTRIDE, bool OUT_HALF>
__global__ __launch_bounds__(256, 2)
void gemm_h_kernel(const __half* __restrict__ A,
                   const __half* __restrict__ Bt,
                   const float* __restrict__ bias,
                   void* __restrict__ Cout) {
    extern __shared__ __align__(128) char smem[];
    const uint32_t sb = smem_u32(smem);

    const int tid  = threadIdx.x;
    const int lane = tid & 31, wid = tid >> 5;
    const int wm = wid >> 1;          // 0..3 : rows wm*32
    const int wn = wid & 1;           // 0..1 : cols wn*64
    const int row0 = blockIdx.y * 128;
    const int col0 = blockIdx.x * 128;

    // Fragment addressing (SW128 xor; smem rows are 64 fp16 = 128B)
    const uint32_t fxor  = (uint32_t)(lane & 7) << 4;
    const uint32_t a_row = (uint32_t)(wm * 32 + (lane & 15)) * 128;
    const uint32_t ahalf = (uint32_t)(lane >> 4) * 16;
    const uint32_t b_row = (uint32_t)(wn * 64 + (lane & 7) + ((lane >> 4) << 3)) * 128;
    const uint32_t bhalf = (uint32_t)((lane >> 3) & 1) * 16;

    auto stageA = [&](int kc, uint32_t nb) {
        #pragma unroll
        for (int i = 0; i < 4; i++) {
            int g = tid + i * 256;                 // 1024 granules (128 rows x 8)
            int r = g >> 3, c16 = g & 7;
            uint32_t dst = nb + (uint32_t)r * 128 + (((uint32_t)c16 * 16) ^ (((uint32_t)(r & 7)) << 4));
            const __half* src = A + (size_t)(row0 + r) * CDIM + kc * 64 + c16 * 8;
            CP_ASYNC16(dst, src);
        }
    };
    auto stageB = [&](int kc, uint32_t nb) {
        #pragma unroll
        for (int i = 0; i < 4; i++) {
            int g = tid + i * 256;                 // 1024 granules (128 rows x 8)
            int r = g >> 3, c16 = g & 7;
            uint32_t dst = nb + 16384u + (uint32_t)r * 128 + (((uint32_t)c16 * 16) ^ (((uint32_t)(r & 7)) << 4));
            const __half* src = Bt + (size_t)(col0 + r) * CDIM + kc * 64 + c16 * 8;
            CP_ASYNC16(dst, src);
        }
    };

    // prologue: stage chunks 0, 1
    stageA(0, sb);               stageB(0, sb);               CP_COMMIT();
    stageA(1, sb + STAGE_BYTES); stageB(1, sb + STAGE_BYTES); CP_COMMIT();

    float acc[2][8][4];
    #pragma unroll
    for (int mt = 0; mt < 2; mt++)
        #pragma unroll
        for (int nt = 0; nt < 8; nt++)
            #pragma unroll
            for (int e = 0; e < 4; e++) acc[mt][nt][e] = 0.0f;

    #pragma unroll 1
    for (int kc = 0; kc < 4; kc++) {
        const uint32_t sbase = sb + (uint32_t)(kc % 3) * STAGE_BYTES;
        if (kc == 3) { CP_WAIT0(); } else { CP_WAIT1(); }
        __syncthreads();

        #pragma unroll
        for (int ks = 0; ks < 4; ks++) {
            uint32_t af[2][4];
            #pragma unroll
            for (int mt = 0; mt < 2; mt++)
                ldsm4(af[mt], sbase + a_row + (uint32_t)mt * 2048 + ((ahalf + ks * 32) ^ fxor));
            uint32_t bf[4][4];
            #pragma unroll
            for (int np = 0; np < 4; np++)
                ldsm4(bf[np], sbase + 16384u + b_row + (uint32_t)np * 2048 + ((bhalf + ks * 32) ^ fxor));
            #pragma unroll
            for (int mt = 0; mt < 2; mt++)
                #pragma unroll
                for (int nt = 0; nt < 8; nt++)
                    mma_f16(acc[mt][nt], af[mt], &bf[nt >> 1][(nt & 1) * 2]);
        }

        if (kc < 2) {
            const uint32_t nb = sb + (uint32_t)((kc + 2) % 3) * STAGE_BYTES;
            stageA(kc + 2, nb);
            stageB(kc + 2, nb);
            CP_COMMIT();
        }
    }
    __syncthreads();

    // epilogue: frags -> smem f32 -> coalesced global (+bias)
    float* Cs = reinterpret_cast<float*>(smem);    // [128][132] = 67.6KB
    #pragma unroll
    for (int mt = 0; mt < 2; mt++) {
        const int r0 = wm * 32 + mt * 16 + (lane >> 2);
        #pragma unroll
        for (int nt = 0; nt < 8; nt++) {
            const int c0 = wn * 64 + nt * 8 + (lane & 3) * 2;
            *reinterpret_cast<float2*>(Cs + r0 * 132 + c0)       = make_float2(acc[mt][nt][0], acc[mt][nt][1]);
            *reinterpret_cast<float2*>(Cs + (r0 + 8) * 132 + c0) = make_float2(acc[mt][nt][2], acc[mt][nt][3]);
        }
    }
    __syncthreads();

    const int t = TSTRIDE ? (blockIdx.y / 288) : 0;
    #pragma unroll
    for (int i = 0; i < 16; i++) {
        int id = tid + i * 256;                    // 4096 float4 slots
        int r = id >> 5, c = (id & 31) * 4;
        float4 v = *reinterpret_cast<const float4*>(Cs + r * 132 + c);
        int n = col0 + c;
        const float4 b4 = *reinterpret_cast<const float4*>(bias + t * TSTRIDE + n);
        v.x += b4.x; v.y += b4.y; v.z += b4.z; v.w += b4.w;
        if (OUT_HALF) {
            *reinterpret_cast<uint2*>(reinterpret_cast<__half*>(Cout) + (size_t)(row0 + r) * NW + n) = f4_to_h4(v);
        } else {
            *reinterpret_cast<float4*>(reinterpret_cast<float*>(Cout) + (size_t)(row0 + r) * NW + n) = v;
        }
    }
}

// ---------------------------------------------------------------------------
// Attention over T=7 per (token, 4-head group), fp16 in / fp16 out.
// ---------------------------------------------------------------------------
__global__ void attn_kernel() {
    const int gw = (blockIdx.x * blockDim.x + threadIdx.x) >> 5;
    const int lane = threadIdx.x & 31;
    const int s = gw >> 1;
    const int half = gw & 1;
    const int hg = lane >> 3, dg = lane & 7;
    const int col = (half * 4 + hg) * 32 + dg * 4;

    float4 q[7], k[7], v[7];
    #pragma unroll
    for (int t = 0; t < 7; t++) {
        const __half* base = g_qkv_h + (size_t)(t * NTOK + s) * NQKV;
        q[t] = h4_to_f4(*reinterpret_cast<const uint2*>(base + col));
        k[t] = h4_to_f4(*reinterpret_cast<const uint2*>(base + 256 + col));
        v[t] = h4_to_f4(*reinterpret_cast<const uint2*>(base + 512 + col));
    }

    const float scale = 0.17677669529663687f;  // 1/sqrt(32)
    float e[7] = {0.f, 0.f, 0.f, 0.f, 0.f, 0.f, 0.f};
    #pragma unroll
    for (int qt = 0; qt < 7; qt++) {
        #pragma unroll
        for (int t = 0; t < 7; t++) {
            float d = q[qt].x * k[t].x + q[qt].y * k[t].y
                    + q[qt].z * k[t].z + q[qt].w * k[t].w;
            d += __shfl_xor_sync(0xffffffffu, d, 1);
            d += __shfl_xor_sync(0xffffffffu, d, 2);
            d += __shfl_xor_sync(0xffffffffu, d, 4);
            const int p = qt * 7 + t;
            if ((p & 7) == dg) e[p >> 3] = __expf(d * scale);
        }
    }

    float4 ctx[7];
    float den[7];
    #pragma unroll
    for (int qt = 0; qt < 7; qt++) { ctx[qt] = make_float4(0, 0, 0, 0); den[qt] = 0.f; }
    #pragma unroll
    for (int qt = 0; qt < 7; qt++) {
        #pragma unroll
        for (int t = 0; t < 7; t++) {
            const int p = qt * 7 + t;
            float eb = __shfl_sync(0xffffffffu, e[p >> 3], p & 7, 8);
            den[qt] += eb;
            ctx[qt].x += eb * v[t].x;
            ctx[qt].y += eb * v[t].y;
            ctx[qt].z += eb * v[t].z;
            ctx[qt].w += eb * v[t].w;
        }
    }
    #pragma unroll
    for (int qt = 0; qt < 7; qt++) {
        const float r = 1.0f / den[qt];
        float4 o = make_float4(ctx[qt].x * r, ctx[qt].y * r, ctx[qt].z * r, ctx[qt].w * r);
        *reinterpret_cast<uint2*>(g_ctx_h + (size_t)(qt * NTOK + s) * CDIM + col) = f4_to_h4(o);
    }
}

// ---------------------------------------------------------------------------
extern "C" void kernel_launch(void* const* d_in, const int* /*in_sizes*/, int /*n_in*/,
                              void* d_out, int /*out_size*/) {
    const float* frames = (const float*)d_in[0];
    const float* temb   = (const float*)d_in[1];
    const float* Wq     = (const float*)d_in[2];
    const float* bq     = (const float*)d_in[3];
    const float* Wk     = (const float*)d_in[4];
    const float* bk     = (const float*)d_in[5];
    const float* Wv     = (const float*)d_in[6];
    const float* bv     = (const float*)d_in[7];
    const float* Wo     = (const float*)d_in[8];
    const float* bo     = (const float*)d_in[9];
    float* out = (float*)d_out;

    void *p_ah, *p_qkv, *p_ctx, *p_wbt, *p_wot, *p_bias;
    cudaGetSymbolAddress(&p_ah,   g_a_h);
    cudaGetSymbolAddress(&p_qkv,  g_qkv_h);
    cudaGetSymbolAddress(&p_ctx,  g_ctx_h);
    cudaGetSymbolAddress(&p_wbt,  g_wbt_h);
    cudaGetSymbolAddress(&p_wot,  g_wot_h);
    cudaGetSymbolAddress(&p_bias, g_bias);

    cudaFuncSetAttribute(gemm_h_kernel<NQKV, NQKV, true>,
                         cudaFuncAttributeMaxDynamicSharedMemorySize, SM_TOTAL);
    cudaFuncSetAttribute(gemm_h_kernel<CDIM, 0, false>,
                         cudaFuncAttributeMaxDynamicSharedMemorySize, SM_TOTAL);

    prep_wt_kernel<<<(NQKV * CDIM + CDIM * CDIM + 255) / 256, 256>>>(Wq, Wk, Wv, Wo);
    prep_bias_kernel<<<(T_ * NQKV + 255) / 256, 256>>>(temb, Wq, bq, Wk, bk, bv);
    prep_frames_kernel<<<(ROWS * CDIM / 4) / 256, 256>>>(frames);

    // QKV projection: [258048 x 256] @ [256 x 768] + bias[t]  -> fp16 qkv
    gemm_h_kernel<NQKV, NQKV, true><<<dim3(6, ROWS / 128), 256, SM_TOTAL>>>(
        (const __half*)p_ah, (const __half*)p_wbt, (const float*)p_bias, p_qkv);

    // Attention (fp16 -> fp16)
    attn_kernel<<<(NTOK * 2 * 32) / 256, 256>>>();

    // Output projection: [258048 x 256] @ [256 x 256] + bo -> f32 out
    gemm_h_kernel<CDIM, 0, false><<<dim3(2, ROWS / 128), 256, SM_TOTAL>>>(
        (const __half*)p_ctx, (const __half*)p_wot, bo, out);
}